// round 9
// baseline (speedup 1.0000x reference)
#include <cuda_runtime.h>

// BlurOutwards: out = (1/20) * sum_{i=0}^{19} D^i(x), D = 3x3 max, zero padding.
// Iterated zero-padded dilation == iterated 3x3 max on the zero-extended image;
// composes across passes: D^{a+b}(x) = D^b(D^a(x)).
//
// Three chained register-pipeline passes (7 + 7 + 5 levels), 1 px/thread,
// TPB=512, 2 CTAs/SM. Key tricks:
//  - corner-square identity: for inputs that are already (2i+1)^2 square maxes
//    (i>=1), the next 3x3 dilation = max of the 4 corner values -> separable
//    2-point maxes (2 FMNMX/level instead of 4). Only pass 1 level 0 needs the
//    full 3-max (its input is the raw image).
//  - edge smem laid out with the level index contiguous; base pointers for
//    both parities precomputed so per-level LDS/STS use immediate offsets.

#define IMH   512
#define IMW   512
#define TPB   512
#define NW    (TPB / 32)       // 16 warps
#define SEGS  3
#define MAX_PLANES 96

__device__ float g_scrA[MAX_PLANES * IMH * IMW];
__device__ float g_scrB[MAX_PLANES * IMH * IMW];

template<int NLEV, bool FIRST, bool WRITE_Y, bool FINAL>
__global__ __launch_bounds__(TPB, 2)
void blur_pass_kernel(const float* __restrict__ in,
                      const float* sum_in,
                      float* sum_out,
                      float* __restrict__ y_out)
{
    const int plane = blockIdx.x;
    const int seg   = blockIdx.y;

    const int r0 = (IMH * seg) / SEGS;
    const int r1 = (IMH * (seg + 1)) / SEGS;

    const size_t pbase = (size_t)plane * IMH * IMW;
    const float* ip = in + pbase;

    const int col  = threadIdx.x;
    const int lane = col & 31;
    const int warp = col >> 5;

    // Edge exchange: [parity][side][warpSlot][level(pad 8)]
    //   side 0 = right edges (lane31 values), side 1 = left edges (lane0).
    //   warpSlot = warp+1; slots 0 and NW+1 stay zero (image-border guard).
    __shared__ float eE[2][2][NW + 2][8];
    for (int k = threadIdx.x; k < 2 * 2 * (NW + 2) * 8; k += TPB)
        (&eE[0][0][0][0])[k] = 0.0f;
    __syncthreads();

    // Precomputed base pointers (level index is the immediate offset).
    const float* ldR0 = &eE[0][0][warp][0];        // left neighbor's right edges
    const float* ldR1 = &eE[1][0][warp][0];
    const float* ldL0 = &eE[0][1][warp + 2][0];    // right neighbor's left edges
    const float* ldL1 = &eE[1][1][warp + 2][0];
    float* stR0 = &eE[0][0][warp + 1][0];          // my right edge (lane31)
    float* stR1 = &eE[1][0][warp + 1][0];
    float* stL0 = &eE[0][1][warp + 1][0];          // my left edge (lane0)
    float* stL1 = &eE[1][1][warp + 1][0];

    // Per-level pipeline state (zero == zero-extension above the strip).
    // a1/a2: for the full-3x3 level: h(prev row), max of prior two h-rows.
    //        for corner levels:      h(prev row), h(2 rows ago).
    float pend[NLEV], a1[NLEV], a2[NLEV], d1[NLEV], d2[NLEV];
#pragma unroll
    for (int i = 0; i < NLEV; ++i) {
        pend[i] = 0.0f; a1[i] = 0.0f; a2[i] = 0.0f; d1[i] = 0.0f; d2[i] = 0.0f;
    }

    const int DELAY = 2 * NLEV;
    const int t0    = r0 - NLEV;          // exact warmup
    const int tend  = r1 - 1 + DELAY;

    const bool isL = (lane == 0);
    const bool isR = (lane == 31);

    int par = 0;
    for (int t = t0; t <= tend; ++t, par ^= 1) {
        const float* eR_rd = par ? ldR1 : ldR0;
        const float* eL_rd = par ? ldL1 : ldL0;
        float* eR_wr = par ? stR0 : stR1;     // write next parity
        float* eL_wr = par ? stL0 : stL1;

        float v = 0.0f;
        if ((unsigned)t < (unsigned)IMH) v = __ldg(&ip[(size_t)t * IMW + col]);

        float incoming = v;                   // y_{i-1} handed to next level
        float sprev    = FIRST ? v : 0.0f;    // running sum pipeline input

#pragma unroll
        for (int i = 0; i < NLEV; ++i) {
            // Horizontal neighbors of the one-row-stale buffered row.
            float p = pend[i];
            float l = __shfl_up_sync(0xffffffffu, p, 1);
            float r = __shfl_down_sync(0xffffffffu, p, 1);
            if (isL) l = eR_rd[i];
            if (isR) r = eL_rd[i];

            float y;
            if (FIRST && i == 0) {
                // Raw-image level: full separable 3x3 max.
                float m3 = fmaxf(fmaxf(l, r), p);
                y = fmaxf(a2[i], m3);
                a2[i] = fmaxf(a1[i], m3);
                a1[i] = m3;
            } else {
                // Input is a (2i+1)^2 square max (i>=1): corner identity.
                float h = fmaxf(l, r);
                y = fmaxf(h, a2[i]);
                a2[i] = a1[i];
                a1[i] = h;
            }

            // Sum pipeline with 2-row delay alignment.
            float s = d2[i] + y;
            d2[i] = d1[i];
            d1[i] = sprev;

            pend[i] = incoming;
            if (isL) eL_wr[i] = incoming;
            if (isR) eR_wr[i] = incoming;
            incoming = y;
            sprev    = s;
        }

        const int orow = t - DELAY;
        if (orow >= r0 && orow < r1) {
            const size_t idx = pbase + (size_t)orow * IMW + col;
            float s = sprev;
            if (!FIRST) s += sum_in[idx];
            sum_out[idx] = FINAL ? s * 0.05f : s;
            if (WRITE_Y) y_out[idx] = incoming;   // == y_NLEV[orow]
        }

        __syncthreads();  // separates this step's edge writes from next reads
    }
}

extern "C" void kernel_launch(void* const* d_in, const int* in_sizes, int n_in,
                              void* d_out, int out_size)
{
    const float* in = (const float*)d_in[0];
    float* out      = (float*)d_out;

    const int planes = in_sizes[0] / (IMH * IMW);   // 96

    float *scrA = nullptr, *scrB = nullptr;
    cudaGetSymbolAddress((void**)&scrA, g_scrA);
    cudaGetSymbolAddress((void**)&scrB, g_scrB);

    dim3 grid(planes, SEGS);

    // Pass 1: levels 1..7 (+ identity term), writes s(0..7) and y7.
    blur_pass_kernel<7, true,  true,  false><<<grid, TPB>>>(in,   nullptr, out, scrA);
    // Pass 2: levels 8..14, accumulates into out, writes y14.
    blur_pass_kernel<7, false, true,  false><<<grid, TPB>>>(scrA, out,     out, scrB);
    // Pass 3: levels 15..19, accumulates and scales by 1/20.
    blur_pass_kernel<5, false, false, true ><<<grid, TPB>>>(scrB, out,     out, nullptr);
}

// round 10
// speedup vs baseline: 1.4399x; 1.4399x over previous
#include <cuda_runtime.h>

// BlurOutwards: out = (1/20) * sum_{i=0}^{19} D^i(x), D = 3x3 max, zero padding.
// Iterated zero-padded dilation == iterated 3x3 max on the zero-extended image;
// composes across passes: D^{a+b}(x) = D^b(D^a(x)).
//
// Three chained register-pipeline passes (7 + 7 + 5 levels), 1 px/thread,
// TPB=512, 2 CTAs/SM — R7 structure, but TWO ROWS PER ITERATION:
//   - one __syncthreads per 2 rows (edge smem is 2-rows skewed),
//   - 4 independent shuffles batched per level per iteration,
//   - per-level delay 3 rows; sum stream delayed with 3 regs/level.

#define IMH   512
#define IMW   512
#define TPB   512
#define NW    (TPB / 32)       // 16 warps
#define SEGS  3
#define MAX_PLANES 96

__device__ float g_scrA[MAX_PLANES * IMH * IMW];
__device__ float g_scrB[MAX_PLANES * IMH * IMW];

template<int NLEV, bool FIRST, bool WRITE_Y, bool FINAL>
__global__ __launch_bounds__(TPB, 2)
void blur_pass_kernel(const float* __restrict__ in,
                      const float* sum_in,
                      float* sum_out,
                      float* __restrict__ y_out)
{
    const int plane = blockIdx.x;
    const int seg   = blockIdx.y;

    const int r0 = (IMH * seg) / SEGS;
    const int r1 = (IMH * (seg + 1)) / SEGS;

    const size_t pbase = (size_t)plane * IMH * IMW;
    const float* ip = in + pbase;

    const int col  = threadIdx.x;
    const int lane = col & 31;
    const int warp = col >> 5;
    const bool isL = (lane == 0);
    const bool isR = (lane == 31);

    // Edge exchange: [parity][side][warpSlot][2*level + sub]
    //   side 0 = right edges (lane31), side 1 = left edges (lane0).
    //   warpSlot = warp+1; slots 0 and NW+1 stay zero (image-border guard).
    __shared__ float eE[2][2][NW + 2][16];
    for (int k = threadIdx.x; k < 2 * 2 * (NW + 2) * 16; k += TPB)
        (&eE[0][0][0][0])[k] = 0.0f;
    __syncthreads();

    // Per-level state (zero == zero-extension above the strip):
    //   pA/pB: received input pair (2 rows stale)
    //   h1:    H of newest processed row;  mx: max of last two H rows
    //   dq*:   3-row delay of the partial-sum stream
    float pA[NLEV], pB[NLEV], h1[NLEV], mx[NLEV];
    float dq1lo[NLEV], dq1hi[NLEV], dq2hi[NLEV];
#pragma unroll
    for (int i = 0; i < NLEV; ++i) {
        pA[i]=0.f; pB[i]=0.f; h1[i]=0.f; mx[i]=0.f;
        dq1lo[i]=0.f; dq1hi[i]=0.f; dq2hi[i]=0.f;
    }

    const int DELAY = 3 * NLEV;
    const int T0    = r0 - NLEV;              // spatial warmup

    int par = 0;
    for (int t = T0; t - DELAY <= r1 - 1; t += 2, par ^= 1) {
        float (*eRd)[NW + 2][16] = eE[par];
        float (*eWr)[NW + 2][16] = eE[par ^ 1];

        // Ingest input rows t, t+1 (zero-extended).
        float u0 = 0.0f, u1 = 0.0f;
        if ((unsigned)t       < (unsigned)IMH) u0 = ip[(size_t)t       * IMW + col];
        if ((unsigned)(t + 1) < (unsigned)IMH) u1 = ip[(size_t)(t + 1) * IMW + col];

        float q0 = FIRST ? u0 : 0.0f;   // partial-sum stream (aligned with u)
        float q1 = FIRST ? u1 : 0.0f;

#pragma unroll
        for (int i = 0; i < NLEV; ++i) {
            float a = pA[i], b = pB[i];
            // Batched independent shuffles for both stale rows.
            float la = __shfl_up_sync(0xffffffffu, a, 1);
            float ra = __shfl_down_sync(0xffffffffu, a, 1);
            float lb = __shfl_up_sync(0xffffffffu, b, 1);
            float rb = __shfl_down_sync(0xffffffffu, b, 1);
            if (isL) { la = eRd[0][warp][2*i];     lb = eRd[0][warp][2*i + 1]; }
            if (isR) { ra = eRd[1][warp + 2][2*i]; rb = eRd[1][warp + 2][2*i + 1]; }
            float HA = fmaxf(fmaxf(la, ra), a);
            float HB = fmaxf(fmaxf(lb, rb), b);

            // Vertical 3-max for the two rows.
            float yA = fmaxf(mx[i], HA);            // y rows t-DELAY-ish pair
            float m2 = fmaxf(h1[i], HA);
            float yB = fmaxf(m2, HB);
            mx[i] = fmaxf(HA, HB);
            h1[i] = HB;

            // Sum stream delayed by 3 rows to align with (yA, yB).
            float sA = dq2hi[i] + yA;
            float sB = dq1lo[i] + yB;
            dq2hi[i] = dq1hi[i];
            dq1hi[i] = q1;
            dq1lo[i] = q0;

            // Hand-off to next level + edge publication for next iteration.
            pA[i] = u0;  pB[i] = u1;
            if (isL) { eWr[1][warp + 1][2*i] = u0;  eWr[1][warp + 1][2*i + 1] = u1; }
            if (isR) { eWr[0][warp + 1][2*i] = u0;  eWr[0][warp + 1][2*i + 1] = u1; }
            u0 = yA;  u1 = yB;
            q0 = sA;  q1 = sB;
        }

        // q0/q1 = s_NLEV rows (t-DELAY, t+1-DELAY); u0/u1 = y_NLEV same rows.
        const int orow = t - DELAY;
        if (orow >= r0 && orow < r1) {
            const size_t idx = pbase + (size_t)orow * IMW + col;
            float s = q0;
            if (!FIRST) s += sum_in[idx];
            sum_out[idx] = FINAL ? s * 0.05f : s;
            if (WRITE_Y) y_out[idx] = u0;
        }
        const int orow2 = orow + 1;
        if (orow2 >= r0 && orow2 < r1) {
            const size_t idx = pbase + (size_t)orow2 * IMW + col;
            float s = q1;
            if (!FIRST) s += sum_in[idx];
            sum_out[idx] = FINAL ? s * 0.05f : s;
            if (WRITE_Y) y_out[idx] = u1;
        }

        __syncthreads();  // separates this iteration's edge writes from next reads
    }
}

extern "C" void kernel_launch(void* const* d_in, const int* in_sizes, int n_in,
                              void* d_out, int out_size)
{
    const float* in = (const float*)d_in[0];
    float* out      = (float*)d_out;

    const int planes = in_sizes[0] / (IMH * IMW);   // 96

    float *scrA = nullptr, *scrB = nullptr;
    cudaGetSymbolAddress((void**)&scrA, g_scrA);
    cudaGetSymbolAddress((void**)&scrB, g_scrB);

    dim3 grid(planes, SEGS);

    // Pass 1: levels 1..7 (+ identity term), writes s(0..7) and y7.
    blur_pass_kernel<7, true,  true,  false><<<grid, TPB>>>(in,   nullptr, out, scrA);
    // Pass 2: levels 8..14, accumulates into out, writes y14.
    blur_pass_kernel<7, false, true,  false><<<grid, TPB>>>(scrA, out,     out, scrB);
    // Pass 3: levels 15..19, accumulates and scales by 1/20.
    blur_pass_kernel<5, false, false, true ><<<grid, TPB>>>(scrB, out,     out, nullptr);
}

// round 11
// speedup vs baseline: 1.4783x; 1.0267x over previous
#include <cuda_runtime.h>

// BlurOutwards: out = (1/20) * sum_{i=0}^{19} D^i(x), D = 3x3 max, zero padding.
// Iterated zero-padded dilation == iterated 3x3 max on the zero-extended image;
// composes across passes: D^{a+b}(x) = D^b(D^a(x)).
//
// Three chained register-pipeline passes (7 + 7 + 5 levels), 1 px/thread,
// TPB=512, 2 CTAs/SM, TWO ROWS PER ITERATION (R10 structure), plus:
//  - corner-square identity: D^{n+1}(f) = max of the 4 corner values of D^n(f)
//    for n>=1  ->  all levels except pass-1 level 0 use 2-point maxes
//    (4 FMNMX per level per 2 rows instead of 8). Zero edge guards supply the
//    padding-zero term the true max requires at image borders.
//  - float2 edge exchange (one LDS.64/STS.64 per side per level).

#define IMH   512
#define IMW   512
#define TPB   512
#define NW    (TPB / 32)       // 16 warps
#define SEGS  3
#define MAX_PLANES 96

__device__ float g_scrA[MAX_PLANES * IMH * IMW];
__device__ float g_scrB[MAX_PLANES * IMH * IMW];

template<int NLEV, bool FIRST, bool WRITE_Y, bool FINAL>
__global__ __launch_bounds__(TPB, 2)
void blur_pass_kernel(const float* __restrict__ in,
                      const float* sum_in,
                      float* sum_out,
                      float* __restrict__ y_out)
{
    const int plane = blockIdx.x;
    const int seg   = blockIdx.y;

    const int r0 = (IMH * seg) / SEGS;
    const int r1 = (IMH * (seg + 1)) / SEGS;

    const size_t pbase = (size_t)plane * IMH * IMW;
    const float* ip = in + pbase;

    const int col  = threadIdx.x;
    const int lane = col & 31;
    const int warp = col >> 5;
    const bool isL = (lane == 0);
    const bool isR = (lane == 31);

    // Edge exchange: [parity][side][warpSlot][level], float2 = (rowA, rowB).
    //   side 0 = right edges (lane31), side 1 = left edges (lane0).
    //   warpSlot = warp+1; slots 0 and NW+1 stay zero (image-border guard).
    __shared__ float2 eE[2][2][NW + 2][8];
    for (int k = threadIdx.x; k < 2 * 2 * (NW + 2) * 8 * 2; k += TPB)
        ((float*)&eE[0][0][0][0])[k] = 0.0f;
    __syncthreads();

    // Per-level state (zero == zero-extension above the strip):
    //   pA/pB: received input row pair (2 rows stale)
    //   corner levels: h1 = H[k-1], h2 = H[k-2]
    //   full level (pass1 i==0): h1 = newest H, h2 = max of last two H rows
    //   dq*: 3-row delay of the partial-sum stream
    float pA[NLEV], pB[NLEV], h1[NLEV], h2[NLEV];
    float dq1lo[NLEV], dq1hi[NLEV], dq2hi[NLEV];
#pragma unroll
    for (int i = 0; i < NLEV; ++i) {
        pA[i]=0.f; pB[i]=0.f; h1[i]=0.f; h2[i]=0.f;
        dq1lo[i]=0.f; dq1hi[i]=0.f; dq2hi[i]=0.f;
    }

    const int DELAY = 3 * NLEV;
    const int T0    = r0 - NLEV;              // spatial warmup

    int par = 0;
    for (int t = T0; t - DELAY <= r1 - 1; t += 2, par ^= 1) {
        float2 (*eRd)[NW + 2][8] = eE[par];
        float2 (*eWr)[NW + 2][8] = eE[par ^ 1];

        // Ingest input rows t, t+1 (zero-extended).
        float u0 = 0.0f, u1 = 0.0f;
        if ((unsigned)t       < (unsigned)IMH) u0 = ip[(size_t)t       * IMW + col];
        if ((unsigned)(t + 1) < (unsigned)IMH) u1 = ip[(size_t)(t + 1) * IMW + col];

        float q0 = FIRST ? u0 : 0.0f;   // partial-sum stream (aligned with u)
        float q1 = FIRST ? u1 : 0.0f;

#pragma unroll
        for (int i = 0; i < NLEV; ++i) {
            float a = pA[i], b = pB[i];
            float la = __shfl_up_sync(0xffffffffu, a, 1);
            float ra = __shfl_down_sync(0xffffffffu, a, 1);
            float lb = __shfl_up_sync(0xffffffffu, b, 1);
            float rb = __shfl_down_sync(0xffffffffu, b, 1);
            if (isL) { float2 e = eRd[0][warp][i];     la = e.x; lb = e.y; }
            if (isR) { float2 e = eRd[1][warp + 2][i]; ra = e.x; rb = e.y; }

            float yA, yB;
            if (FIRST && i == 0) {
                // Raw-image level: full separable 3x3 max.
                float HA = fmaxf(fmaxf(la, ra), a);
                float HB = fmaxf(fmaxf(lb, rb), b);
                yA = fmaxf(h2[i], HA);            // h2 = max(H[k-2],H[k-1])
                float m2 = fmaxf(h1[i], HA);
                yB = fmaxf(m2, HB);
                h2[i] = fmaxf(HA, HB);
                h1[i] = HB;
            } else {
                // Corner identity: input is a square max (radius >= 1).
                float HA = fmaxf(la, ra);         // H[k]
                float HB = fmaxf(lb, rb);         // H[k+1]
                yA = fmaxf(h2[i], HA);            // y[k-1] = max(H[k-2], H[k])
                yB = fmaxf(h1[i], HB);            // y[k]   = max(H[k-1], H[k+1])
                h2[i] = HA;
                h1[i] = HB;
            }

            // Sum stream delayed by 3 rows to align with (yA, yB).
            float sA = dq2hi[i] + yA;
            float sB = dq1lo[i] + yB;
            dq2hi[i] = dq1hi[i];
            dq1hi[i] = q1;
            dq1lo[i] = q0;

            // Hand-off to next level + edge publication for next iteration.
            pA[i] = u0;  pB[i] = u1;
            if (isL) eWr[1][warp + 1][i] = make_float2(u0, u1);
            if (isR) eWr[0][warp + 1][i] = make_float2(u0, u1);
            u0 = yA;  u1 = yB;
            q0 = sA;  q1 = sB;
        }

        // q0/q1 = s_NLEV rows (t-DELAY, t+1-DELAY); u0/u1 = y_NLEV same rows.
        const int orow = t - DELAY;
        if (orow >= r0 && orow < r1) {
            const size_t idx = pbase + (size_t)orow * IMW + col;
            float s = q0;
            if (!FIRST) s += sum_in[idx];
            sum_out[idx] = FINAL ? s * 0.05f : s;
            if (WRITE_Y) y_out[idx] = u0;
        }
        const int orow2 = orow + 1;
        if (orow2 >= r0 && orow2 < r1) {
            const size_t idx = pbase + (size_t)orow2 * IMW + col;
            float s = q1;
            if (!FIRST) s += sum_in[idx];
            sum_out[idx] = FINAL ? s * 0.05f : s;
            if (WRITE_Y) y_out[idx] = u1;
        }

        __syncthreads();  // separates this iteration's edge writes from next reads
    }
}

extern "C" void kernel_launch(void* const* d_in, const int* in_sizes, int n_in,
                              void* d_out, int out_size)
{
    const float* in = (const float*)d_in[0];
    float* out      = (float*)d_out;

    const int planes = in_sizes[0] / (IMH * IMW);   // 96

    float *scrA = nullptr, *scrB = nullptr;
    cudaGetSymbolAddress((void**)&scrA, g_scrA);
    cudaGetSymbolAddress((void**)&scrB, g_scrB);

    dim3 grid(planes, SEGS);

    // Pass 1: levels 1..7 (+ identity term), writes s(0..7) and y7.
    blur_pass_kernel<7, true,  true,  false><<<grid, TPB>>>(in,   nullptr, out, scrA);
    // Pass 2: levels 8..14, accumulates into out, writes y14.
    blur_pass_kernel<7, false, true,  false><<<grid, TPB>>>(scrA, out,     out, scrB);
    // Pass 3: levels 15..19, accumulates and scales by 1/20.
    blur_pass_kernel<5, false, false, true ><<<grid, TPB>>>(scrB, out,     out, nullptr);
}